// round 14
// baseline (speedup 1.0000x reference)
#include <cuda_runtime.h>
#include <cuda_fp16.h>
#include <cstdint>

#define D        128
#define NUM_DOW  7
#define NUM_TOD  288
#define NROWS    (NUM_DOW * NUM_TOD)   // 2016
#define RPB      8                     // rows per build block -> 252 blocks
#define TPW      16                    // tokens per warp in gather

// Precomputed output rows for every (dow, tod) pair, fp16: 2016*128*2B = 504 KB.
__device__ __align__(16) __half g_table[NROWS * D];

// ---------------------------------------------------------------------------
// Kernel 1: build the 2016-row table (fp32 math, fp16 store).
// The FMA loop previously read W2 straight from L2 (L1 is flushed per launch)
// with MLP~4 -> ~5us latency-bound. Now: cooperative prefetch of all of W2
// (64 KB) into dynamic smem with MLP=16, then the FMA loop runs entirely out
// of smem (conflict-free LDS.32 for w, broadcast LDS.128 for h).
// 252 blocks x 256 threads; thread = (e, half), 4 rows each.
// ---------------------------------------------------------------------------
__global__ __launch_bounds__(256)
void build_table_kernel(const float* __restrict__ W1,
                        const float* __restrict__ b1,
                        const float* __restrict__ W2,
                        const float* __restrict__ b2) {
    extern __shared__ __align__(16) float smem[];
    float* W2s = smem;                 // [D][D] = 64 KB, layout identical to W2
    float* h   = smem + D * D;         // [RPB][D] = 4 KB

    const int tid   = threadIdx.x;
    const int e     = tid & (D - 1);
    const int half  = tid >> 7;
    const int rbase = half * (RPB / 2);
    const int row0  = blockIdx.x * RPB;

    // ---- prefetch W2 into smem: 4096 float4, 16 per thread, MLP=16 --------
    {
        const float4* __restrict__ src = (const float4*)W2;
        float4*                    dst = (float4*)W2s;
        #pragma unroll
        for (int k = 0; k < 16; k++)
            dst[tid + 256 * k] = __ldcg(src + tid + 256 * k);
    }

    // ---- hidden rows -------------------------------------------------------
    const float b1e = __ldg(b1 + e);
    #pragma unroll
    for (int i = 0; i < RPB / 2; i++) {
        const int r   = rbase + i;
        const int row = row0 + r;
        const int dow = row / NUM_TOD;
        const int tod = row - dow * NUM_TOD;
        const float v = __ldg(W1 + dow * D + e)
                      + __ldg(W1 + (NUM_DOW + tod) * D + e) + b1e;
        h[r * D + e] = fmaxf(v, 0.0f);
    }
    __syncthreads();

    // ---- FMA phase: everything from smem ----------------------------------
    float acc[RPB / 2];
    const float b2e = __ldg(b2 + e);
    #pragma unroll
    for (int i = 0; i < RPB / 2; i++) acc[i] = b2e;

    const float4* __restrict__ h4 = (const float4*)h;   // [RPB][32]

    #pragma unroll 4
    for (int d4 = 0; d4 < D / 4; d4++) {
        // lanes read consecutive e -> conflict-free LDS.32
        const float w0 = W2s[(4 * d4 + 0) * D + e];
        const float w1 = W2s[(4 * d4 + 1) * D + e];
        const float w2 = W2s[(4 * d4 + 2) * D + e];
        const float w3 = W2s[(4 * d4 + 3) * D + e];
        #pragma unroll
        for (int i = 0; i < RPB / 2; i++) {
            const float4 hv = h4[(rbase + i) * (D / 4) + d4];  // broadcast
            acc[i] = fmaf(hv.x, w0, acc[i]);
            acc[i] = fmaf(hv.y, w1, acc[i]);
            acc[i] = fmaf(hv.z, w2, acc[i]);
            acc[i] = fmaf(hv.w, w3, acc[i]);
        }
    }

    #pragma unroll
    for (int i = 0; i < RPB / 2; i++)
        g_table[(size_t)(row0 + rbase + i) * D + e] = __float2half(acc[i]);
}

// ---------------------------------------------------------------------------
// Kernel 2: gather (unchanged from the proven 14.3us version).
// 16 tokens/warp, paired-row LDG.128 (one load serves two tokens), __ldcg
// L1 bypass, STG.256 stores. ntok % 16 == 0 (131072).
// ---------------------------------------------------------------------------
__global__ __launch_bounds__(256)
void gather_kernel(const int2* __restrict__ TE,   // [ntok] (dow_raw, tod_raw)
                   float* __restrict__ out,       // [ntok * 128] fp32
                   int ntok) {
    const int warp = (int)((blockIdx.x * blockDim.x + threadIdx.x) >> 5);
    const int lane = threadIdx.x & 31;
    const int half = lane >> 4;        // which token of each pair
    const int sub  = lane & 15;        // 16 B chunk within the 256 B row
    const int t0   = warp * TPW;
    if (t0 >= ntok) return;

    const int2 te = __ldg(TE + t0 + (lane & 15));
    const unsigned myrow =
        ((unsigned)te.x % NUM_DOW) * NUM_TOD + ((unsigned)te.y % NUM_TOD);

    unsigned rows[TPW / 2];
    #pragma unroll
    for (int p = 0; p < TPW / 2; p++)          // row for token t0 + 2p + half
        rows[p] = __shfl_sync(0xFFFFFFFFu, myrow, 2 * p + half);

    const float4* __restrict__ tab = (const float4*)g_table;  // 16 f4 per row

    float4 v[TPW / 2];
    #pragma unroll
    for (int p = 0; p < TPW / 2; p++)          // 8 independent L2-only reads
        v[p] = __ldcg(tab + (size_t)rows[p] * (D / 8) + sub);

    #pragma unroll
    for (int p = 0; p < TPW / 2; p++) {
        const __half2* hp = (const __half2*)&v[p];
        const float2 f0 = __half22float2(hp[0]);
        const float2 f1 = __half22float2(hp[1]);
        const float2 f2 = __half22float2(hp[2]);
        const float2 f3 = __half22float2(hp[3]);
        float* dst = out + (size_t)(t0 + 2 * p + half) * D + 8 * sub;
        asm volatile(
            "st.global.v8.f32 [%0], {%1,%2,%3,%4,%5,%6,%7,%8};"
            :: "l"(dst),
               "f"(f0.x), "f"(f0.y), "f"(f1.x), "f"(f1.y),
               "f"(f2.x), "f"(f2.y), "f"(f3.x), "f"(f3.y)
            : "memory");
    }
}

// ---------------------------------------------------------------------------
// Inputs (metadata order): TE, T, W1, b1, W2, b2. T unused.
// Output: [B, S, 1, D] float32 — contiguous, identical to [ntok, D].
// ---------------------------------------------------------------------------
extern "C" void kernel_launch(void* const* d_in, const int* in_sizes, int n_in,
                              void* d_out, int out_size) {
    const int2*  TE = (const int2*)d_in[0];
    const float* W1 = (const float*)d_in[2];
    const float* b1 = (const float*)d_in[3];
    const float* W2 = (const float*)d_in[4];
    const float* b2 = (const float*)d_in[5];

    const int ntok = in_sizes[0] / 2;   // B*S = 131072 (multiple of 16)

    // 64 KB W2 + 4 KB h of dynamic smem (static limit is 48 KB).
    const int smem_bytes = (D * D + RPB * D) * (int)sizeof(float);
    static bool attr_set = false;
    if (!attr_set) {
        cudaFuncSetAttribute(build_table_kernel,
                             cudaFuncAttributeMaxDynamicSharedMemorySize,
                             smem_bytes);
        attr_set = true;
    }

    build_table_kernel<<<NROWS / RPB, 256, smem_bytes>>>(W1, b1, W2, b2);

    // 16 tokens/warp, 8 warps/block -> 128 tokens per block.
    const int nblocks = (ntok + 8 * TPW - 1) / (8 * TPW);   // 1024
    gather_kernel<<<nblocks, 256>>>(TE, (float*)d_out, ntok);
}